// round 2
// baseline (speedup 1.0000x reference)
#include <cuda_runtime.h>
#include <cuda_fp16.h>
#include <cstdint>
#include <cstddef>

// Problem constants (fixed by the dataset)
#define M_DIM 8192      // 4 * 2048
#define K_DIM 4096
#define N_DIM 11008
#define NPACK (N_DIM / 8)   // 1376
#define KPACK (K_DIM / 8)   // 512

// GEMM tiling
#define BM 128
#define BN 128
#define BK 32
#define A_LD 40    // BK + 8 halves (80B row: conflict-free ldmatrix)
#define B_LD 136   // BN + 8 halves (272B row: conflict-free trans ldmatrix)
#define NT (K_DIM / BK)   // 128 k-tiles

// 90 MB fp16 dequantized weight scratch (device global: allocation-free rule)
__device__ __half g_wh[(size_t)K_DIM * N_DIM];

// ---------------------------------------------------------------------------
// Kernel 1: dequantize int4 GPTQ weights -> fp16 [K, N]
//   weight_int[k][n] = (qweight[k/8][n] >> 4*(k%8)) & 15
//   zeros[g][n]      = (qzeros[g][n/8] >> 4*(n%8)) & 15
//   w16 = fp16( (w - z) * s )   with g = k / 128
// Scales arrive from the harness most likely upcast to fp32 (fp16 is not a
// documented harness dtype). Probe element 0: real scales are in
// (0.001, 0.021); an fp16-packed buffer read as float is ~2^-87 garbage, so
// the range check deterministically selects the right layout.
// ---------------------------------------------------------------------------
__global__ void dequant_kernel(const int* __restrict__ qweight,
                               const int* __restrict__ qzeros,
                               const void* __restrict__ scales_raw) {
    int pr = blockIdx.y;                         // packed k row: 0..511
    int n  = blockIdx.x * 256 + threadIdx.x;     // 43 * 256 == 11008 exactly
    int g  = pr >> 4;                            // (pr*8)/128

    const float* sf = (const float*)scales_raw;
    float probe = sf[0];
    bool is_f32 = (probe > 5e-4f && probe < 5e-2f);

    uint32_t q  = (uint32_t)qweight[(size_t)pr * N_DIM + n];
    uint32_t zq = (uint32_t)qzeros[(size_t)g * NPACK + (n >> 3)];
    float z = (float)((zq >> (4 * (n & 7))) & 15u);
    float s = is_f32 ? sf[(size_t)g * N_DIM + n]
                     : __half2float(((const __half*)scales_raw)[(size_t)g * N_DIM + n]);

    size_t base = (size_t)(pr * 8) * N_DIM + n;
#pragma unroll
    for (int j = 0; j < 8; j++) {
        float w = (float)((q >> (4 * j)) & 15u);
        g_wh[base + (size_t)j * N_DIM] = __float2half_rn((w - z) * s);
    }
}

// ---------------------------------------------------------------------------
// PTX helpers
// ---------------------------------------------------------------------------
__device__ __forceinline__ void ldmatrix_x4(uint32_t& r0, uint32_t& r1,
                                            uint32_t& r2, uint32_t& r3,
                                            uint32_t addr) {
    asm volatile("ldmatrix.sync.aligned.m8n8.x4.shared.b16 {%0,%1,%2,%3}, [%4];"
                 : "=r"(r0), "=r"(r1), "=r"(r2), "=r"(r3) : "r"(addr));
}

__device__ __forceinline__ void ldmatrix_x4_trans(uint32_t& r0, uint32_t& r1,
                                                  uint32_t& r2, uint32_t& r3,
                                                  uint32_t addr) {
    asm volatile("ldmatrix.sync.aligned.m8n8.x4.trans.shared.b16 {%0,%1,%2,%3}, [%4];"
                 : "=r"(r0), "=r"(r1), "=r"(r2), "=r"(r3) : "r"(addr));
}

__device__ __forceinline__ void mma16816(float* c, const uint32_t* a, const uint32_t* b) {
    asm volatile(
        "mma.sync.aligned.m16n8k16.row.col.f32.f16.f16.f32 "
        "{%0,%1,%2,%3}, {%4,%5,%6,%7}, {%8,%9}, {%0,%1,%2,%3};"
        : "+f"(c[0]), "+f"(c[1]), "+f"(c[2]), "+f"(c[3])
        : "r"(a[0]), "r"(a[1]), "r"(a[2]), "r"(a[3]), "r"(b[0]), "r"(b[1]));
}

// ---------------------------------------------------------------------------
// Kernel 2: C[M,N] = fp16(x) @ Wh, fp32 accum, output rounded through fp16
// 128x128x32 block tile, 256 threads (8 warps: 2 over M x 4 over N),
// warp tile 64x32 = 4x4 m16n8k16 fragments.
// ---------------------------------------------------------------------------
__global__ __launch_bounds__(256, 2)
void gemm_kernel(const float* __restrict__ x, float* __restrict__ out) {
    __shared__ __half As[BM * A_LD];
    __shared__ __half Bs[BK * B_LD];

    const int tid    = threadIdx.x;
    const int lane   = tid & 31;
    const int wid    = tid >> 5;
    const int warp_m = wid & 1;    // 0..1  (64 rows each)
    const int warp_n = wid >> 1;   // 0..3  (32 cols each)
    const int m0 = blockIdx.y * BM;
    const int n0 = blockIdx.x * BN;

    float acc[4][4][4];
#pragma unroll
    for (int i = 0; i < 4; i++)
#pragma unroll
        for (int j = 0; j < 4; j++)
#pragma unroll
            for (int k = 0; k < 4; k++) acc[i][j][k] = 0.f;

    // Staging registers for the global->smem pipeline
    float4 areg[4];
    uint4  breg[2];

    auto loadA = [&](int k0) {
#pragma unroll
        for (int i = 0; i < 4; i++) {
            int idx = tid + i * 256;            // 1024 float4 chunks
            int r = idx >> 3, c = idx & 7;      // 128 rows x 8 float4
            areg[i] = *(const float4*)(x + (size_t)(m0 + r) * K_DIM + k0 + c * 4);
        }
    };
    auto loadB = [&](int k0) {
#pragma unroll
        for (int i = 0; i < 2; i++) {
            int idx = tid + i * 256;            // 512 uint4 chunks
            int r = idx >> 4, c = idx & 15;     // 32 rows x 16 uint4
            breg[i] = *(const uint4*)(g_wh + (size_t)(k0 + r) * N_DIM + n0 + c * 8);
        }
    };
    auto storeA = [&]() {
#pragma unroll
        for (int i = 0; i < 4; i++) {
            int idx = tid + i * 256;
            int r = idx >> 3, c = idx & 7;
            __half2 h0 = __floats2half2_rn(areg[i].x, areg[i].y);
            __half2 h1 = __floats2half2_rn(areg[i].z, areg[i].w);
            *(__half2*)(As + r * A_LD + c * 4)     = h0;
            *(__half2*)(As + r * A_LD + c * 4 + 2) = h1;
        }
    };
    auto storeB = [&]() {
#pragma unroll
        for (int i = 0; i < 2; i++) {
            int idx = tid + i * 256;
            int r = idx >> 4, c = idx & 15;
            *(uint4*)(Bs + r * B_LD + c * 8) = breg[i];
        }
    };

    auto compute = [&]() {
#pragma unroll
        for (int ks = 0; ks < 2; ks++) {
            const int kk = ks * 16;
            uint32_t a[4][4];
#pragma unroll
            for (int mi = 0; mi < 4; mi++) {
                int row = warp_m * 64 + mi * 16 + (lane & 15);
                int col = kk + 8 * (lane >> 4);
                uint32_t addr = (uint32_t)__cvta_generic_to_shared(As + row * A_LD + col);
                ldmatrix_x4(a[mi][0], a[mi][1], a[mi][2], a[mi][3], addr);
            }
            uint32_t b[4][2];
#pragma unroll
            for (int nh = 0; nh < 2; nh++) {
                // x4.trans: tile0 = (k0-7,n0-7), tile1 = (k8-15,n0-7),
                //           tile2 = (k0-7,n8-15), tile3 = (k8-15,n8-15)
                int trow = kk + (lane & 7) + 8 * ((lane >> 3) & 1);
                int tcol = warp_n * 32 + nh * 16 + 8 * (lane >> 4);
                uint32_t addr = (uint32_t)__cvta_generic_to_shared(Bs + trow * B_LD + tcol);
                uint32_t r0, r1, r2, r3;
                ldmatrix_x4_trans(r0, r1, r2, r3, addr);
                b[nh * 2 + 0][0] = r0; b[nh * 2 + 0][1] = r1;
                b[nh * 2 + 1][0] = r2; b[nh * 2 + 1][1] = r3;
            }
#pragma unroll
            for (int mi = 0; mi < 4; mi++)
#pragma unroll
                for (int ni = 0; ni < 4; ni++)
                    mma16816(acc[mi][ni], a[mi], b[ni]);
        }
    };

    // Pipeline: prefetch next tile into registers while computing current
    loadA(0); loadB(0);
    storeA(); storeB();
    __syncthreads();
#pragma unroll 1
    for (int t = 0; t < NT; t++) {
        if (t + 1 < NT) { loadA((t + 1) * BK); loadB((t + 1) * BK); }
        compute();
        __syncthreads();
        if (t + 1 < NT) { storeA(); storeB(); __syncthreads(); }
    }

    // Epilogue: round through fp16 (reference casts the fp16 matmul result
    // back to fp32), write as float2 pairs.
    const int g4 = lane >> 2, t4 = lane & 3;
#pragma unroll
    for (int mi = 0; mi < 4; mi++) {
#pragma unroll
        for (int ni = 0; ni < 4; ni++) {
            int row = m0 + warp_m * 64 + mi * 16 + g4;
            int col = n0 + warp_n * 32 + ni * 8 + t4 * 2;
            float2 v0, v1;
            v0.x = __half2float(__float2half_rn(acc[mi][ni][0]));
            v0.y = __half2float(__float2half_rn(acc[mi][ni][1]));
            v1.x = __half2float(__float2half_rn(acc[mi][ni][2]));
            v1.y = __half2float(__float2half_rn(acc[mi][ni][3]));
            *(float2*)(out + (size_t)row * N_DIM + col)       = v0;
            *(float2*)(out + (size_t)(row + 8) * N_DIM + col) = v1;
        }
    }
}

// ---------------------------------------------------------------------------
extern "C" void kernel_launch(void* const* d_in, const int* in_sizes, int n_in,
                              void* d_out, int out_size) {
    const float* x       = (const float*)d_in[0];
    const int*   qweight = (const int*)d_in[1];
    const int*   qzeros  = (const int*)d_in[2];
    const void*  scales  = d_in[3];
    float* out = (float*)d_out;

    // 1) dequant int4 -> fp16 scratch (43*256 == 11008 columns exactly)
    dequant_kernel<<<dim3(43, KPACK), 256>>>(qweight, qzeros, scales);

    // 2) tensor-core GEMM: grid 86 x 64
    gemm_kernel<<<dim3(N_DIM / BN, M_DIM / BM), 256>>>(x, out);
}